// round 15
// baseline (speedup 1.0000x reference)
#include <cuda_runtime.h>
#include <cstdint>

// MultiScaleDeformableAttention — GB300
// value:              (8, 22223, 8, 32)  float32
// sampling_locations: (8, 900, 8, 4, 4, 2) float32
// attention_weights:  (8, 900, 8, 4, 4) float32
// out:                (8, 900, 256) float32
//
// R13 champion body (pinned (b,h) CTAs + 3-tier cache policy: lvl0 __ldcs,
// lvl1 __ldcg, lvl2/3 __ldg) with a doubled per-warp MLP:
//   grid = 296 CTAs x 512 threads. CTA cid and cid+148 map to the SAME SM
//   (classic LUT / CLC modular placement), so both half-CTAs of a (bh,half)
//   share L1 -> pinning preserved, warps/SM still 32, but the 512-thread CTA
//   lifts the reg budget to ~128/thread.
//   Each warp processes TWO query-tasks at once: Phase A for both (q, q+32),
//   then Phase B issues both tasks' loads level-interleaved (up to 32
//   LDG.128 in flight) before consuming.

#define BS  8
#define NQ  900
#define NH  8
#define DC  32
#define NL  4
#define NPT 4
#define NKEYS 22223
#define KS4 (NH * DC / 4)        // float4s per key = 64
#define QHALF (NQ / 2)           // 450
#define QMAIN 396                // queries handled by the pinned pair
#define QREST (QHALF - QMAIN)    // 54 leftover per (bh,half)
#define NHELP 40                 // helper CTAs total (20 per sub-grid)
#define TOTREST (128 * QREST)    // 6912 leftover tasks
#define NSTREAM (NHELP * 16)     // 640 helper warp-streams
#define FULLM 0xffffffffu

// Phase A for one task: fills 4 offsets + 4 folded weights per level.
__device__ __forceinline__ void make_desc(
    int task, int g,
    const float2* __restrict__ loc2, const float* __restrict__ aw,
    int o[NL][4], float w[NL][4])
{
    const int Hs[NL]     = {100, 50, 25, 13};
    const int Ws[NL]     = {167, 84, 42, 21};
    const int starts[NL] = {0, 16700, 20900, 21950};

    #pragma unroll
    for (int lvl = 0; lvl < NL; ++lvl) {
        const int H = Hs[lvl];
        const int W = Ws[lvl];
        const int start = starts[lvl];

        const int li = (task * NL + lvl) * NPT + g;
        const float2 l2 = __ldcs(loc2 + li);
        const float  wt = __ldcs(aw + li);

        const float x = l2.x * (float)W - 0.5f;
        const float y = l2.y * (float)H - 0.5f;
        const float xf = floorf(x);
        const float yf = floorf(y);
        const int x0 = (int)xf;
        const int y0 = (int)yf;
        const int x1 = x0 + 1;
        const int y1 = y0 + 1;

        float wx1 = x - xf;
        float wx0 = 1.0f - wx1;
        float wy1 = y - yf;
        float wy0 = 1.0f - wy1;

        if (x0 < 0 || x0 > W - 1) wx0 = 0.0f;
        if (x1 < 0 || x1 > W - 1) wx1 = 0.0f;
        if (y0 < 0 || y0 > H - 1) wy0 = 0.0f;
        if (y1 < 0 || y1 > H - 1) wy1 = 0.0f;
        const int x0c = min(max(x0, 0), W - 1);
        const int x1c = min(max(x1, 0), W - 1);
        const int y0c = min(max(y0, 0), H - 1);
        const int y1c = min(max(y1, 0), H - 1);

        w[lvl][0] = wt * wx0 * wy0;
        w[lvl][1] = wt * wx1 * wy0;
        w[lvl][2] = wt * wx0 * wy1;
        w[lvl][3] = wt * wx1 * wy1;

        const int r0 = start + y0c * W;
        const int r1 = start + y1c * W;
        o[lvl][0] = (r0 + x0c) * KS4;
        o[lvl][1] = (r0 + x1c) * KS4;
        o[lvl][2] = (r1 + x0c) * KS4;
        o[lvl][3] = (r1 + x1c) * KS4;
    }
}

// Tiered 4-corner load for one (task, level).
__device__ __forceinline__ void load4(
    const float4* __restrict__ v4, const int o[4], int lvl,
    float4& a, float4& c, float4& d, float4& e)
{
    if (lvl == 0) {
        a = __ldcs(v4 + o[0]);  c = __ldcs(v4 + o[1]);
        d = __ldcs(v4 + o[2]);  e = __ldcs(v4 + o[3]);
    } else if (lvl == 1) {
        a = __ldcg(v4 + o[0]);  c = __ldcg(v4 + o[1]);
        d = __ldcg(v4 + o[2]);  e = __ldcg(v4 + o[3]);
    } else {
        a = __ldg(v4 + o[0]);   c = __ldg(v4 + o[1]);
        d = __ldg(v4 + o[2]);   e = __ldg(v4 + o[3]);
    }
}

// Process a pair of tasks with interleaved loads (task1 optional).
__device__ __forceinline__ void process_pair(
    int task0, int task1, bool has1,
    const float4* __restrict__ v4,
    const float2* __restrict__ loc2,
    const float*  __restrict__ aw,
    float* __restrict__ out,
    int g, int cp)
{
    int   o0[NL][4], o1[NL][4];
    float w0[NL][4], w1[NL][4];

    make_desc(task0, g, loc2, aw, o0, w0);
    const int t1 = has1 ? task1 : task0;
    make_desc(t1, g, loc2, aw, o1, w1);

    float4 acc0 = make_float4(0.f, 0.f, 0.f, 0.f);
    float4 acc1 = make_float4(0.f, 0.f, 0.f, 0.f);

    #pragma unroll
    for (int lvl = 0; lvl < NL; ++lvl) {
        float4 a0, c0, d0, e0, a1, c1, d1, e1;
        load4(v4, o0[lvl], lvl, a0, c0, d0, e0);
        load4(v4, o1[lvl], lvl, a1, c1, d1, e1);

        acc0.x += a0.x * w0[lvl][0] + c0.x * w0[lvl][1] + d0.x * w0[lvl][2] + e0.x * w0[lvl][3];
        acc0.y += a0.y * w0[lvl][0] + c0.y * w0[lvl][1] + d0.y * w0[lvl][2] + e0.y * w0[lvl][3];
        acc0.z += a0.z * w0[lvl][0] + c0.z * w0[lvl][1] + d0.z * w0[lvl][2] + e0.z * w0[lvl][3];
        acc0.w += a0.w * w0[lvl][0] + c0.w * w0[lvl][1] + d0.w * w0[lvl][2] + e0.w * w0[lvl][3];

        acc1.x += a1.x * w1[lvl][0] + c1.x * w1[lvl][1] + d1.x * w1[lvl][2] + e1.x * w1[lvl][3];
        acc1.y += a1.y * w1[lvl][0] + c1.y * w1[lvl][1] + d1.y * w1[lvl][2] + e1.y * w1[lvl][3];
        acc1.z += a1.z * w1[lvl][0] + c1.z * w1[lvl][1] + d1.z * w1[lvl][2] + e1.z * w1[lvl][3];
        acc1.w += a1.w * w1[lvl][0] + c1.w * w1[lvl][1] + d1.w * w1[lvl][2] + e1.w * w1[lvl][3];
    }

    #pragma unroll
    for (int m = 8; m <= 16; m <<= 1) {
        acc0.x += __shfl_xor_sync(FULLM, acc0.x, m);
        acc0.y += __shfl_xor_sync(FULLM, acc0.y, m);
        acc0.z += __shfl_xor_sync(FULLM, acc0.z, m);
        acc0.w += __shfl_xor_sync(FULLM, acc0.w, m);
        acc1.x += __shfl_xor_sync(FULLM, acc1.x, m);
        acc1.y += __shfl_xor_sync(FULLM, acc1.y, m);
        acc1.z += __shfl_xor_sync(FULLM, acc1.z, m);
        acc1.w += __shfl_xor_sync(FULLM, acc1.w, m);
    }

    if (g == 0) {
        ((float4*)out)[(size_t)task0 * (DC / 4) + cp] = acc0;
        if (has1)
            ((float4*)out)[(size_t)task1 * (DC / 4) + cp] = acc1;
    }
}

__global__ __launch_bounds__(512, 1) void msda_kernel(
    const float* __restrict__ value,
    const float* __restrict__ loc,
    const float* __restrict__ aw,
    float* __restrict__ out)
{
    const int cid  = blockIdx.x;
    const int sub  = (cid >= 148) ? 1 : 0;     // which half-CTA of the pair
    const int p    = cid - sub * 148;          // pinned id 0..147
    const int tid  = threadIdx.x;
    const int wid  = tid >> 5;                 // 0..15
    const int lane = tid & 31;
    const int g  = lane >> 3;
    const int cp = lane & 7;

    const float4* __restrict__ val4 = (const float4*)value;
    const float2* __restrict__ loc2 = (const float2*)loc;

    if (p < 128) {
        // pinned pair: (bh, half); this half-CTA owns warp-slots sub*16+wid
        const int bh   = p >> 1;
        const int half = p & 1;
        const int b    = bh >> 3;
        const int h    = bh & (NH - 1);
        const int w    = sub * 16 + wid;       // 0..31

        const float4* __restrict__ v4 =
            val4 + ((size_t)(b * NKEYS) * NH + h) * (DC / 4) + cp;

        for (int ql = w; ql < QMAIN; ql += 64) {
            const int ql1  = ql + 32;
            const bool has1 = (ql1 < QMAIN);
            const int q0   = half * QHALF + ql;
            const int q1   = half * QHALF + (has1 ? ql1 : ql);
            const int task0 = (b * NQ + q0) * NH + h;
            const int task1 = (b * NQ + q1) * NH + h;
            process_pair(task0, task1, has1, v4, loc2, aw, out, g, cp);
        }
    } else {
        // helper: stream over leftover tasks, two per iteration
        const int j   = (p - 128) + sub * 20;  // 0..39
        const int sid = j * 16 + wid;          // 0..639

        for (int k = 0; ; k += 2) {
            const int t0 = sid + k * NSTREAM;
            if (t0 >= TOTREST) break;
            const int t1f = t0 + NSTREAM;
            const bool has1 = (t1f < TOTREST);

            // decode t0
            const int bhh0  = t0 / QREST;
            const int rem0  = t0 - bhh0 * QREST;
            const int bh0   = bhh0 >> 1;
            const int half0 = bhh0 & 1;
            const int b0    = bh0 >> 3;
            const int h0    = bh0 & (NH - 1);
            const int q0    = half0 * QHALF + QMAIN + rem0;
            const int task0 = (b0 * NQ + q0) * NH + h0;

            // decode t1 (same (b,h) guaranteed? no — decode separately)
            const int tt   = has1 ? t1f : t0;
            const int bhh1  = tt / QREST;
            const int rem1  = tt - bhh1 * QREST;
            const int bh1   = bhh1 >> 1;
            const int half1 = bhh1 & 1;
            const int b1    = bh1 >> 3;
            const int h1    = bh1 & (NH - 1);
            const int q1    = half1 * QHALF + QMAIN + rem1;
            const int task1 = (b1 * NQ + q1) * NH + h1;

            // helper pairs may straddle (b,h): use per-task base pointers by
            // folding the (b,h) base into the offsets via two process calls
            // only when bases differ; same base (common) uses the pair path.
            const float4* __restrict__ v40 =
                val4 + ((size_t)(b0 * NKEYS) * NH + h0) * (DC / 4) + cp;
            if (has1 && b0 == b1 && h0 == h1) {
                process_pair(task0, task1, true, v40, loc2, aw, out, g, cp);
            } else {
                process_pair(task0, task0, false, v40, loc2, aw, out, g, cp);
                if (has1) {
                    const float4* __restrict__ v41 =
                        val4 + ((size_t)(b1 * NKEYS) * NH + h1) * (DC / 4) + cp;
                    process_pair(task1, task1, false, v41, loc2, aw, out, g, cp);
                }
            }
        }
    }
}

extern "C" void kernel_launch(void* const* d_in, const int* in_sizes, int n_in,
                              void* d_out, int out_size)
{
    const float* value = (const float*)d_in[0];
    const float* loc   = (const float*)d_in[1];
    const float* aw    = (const float*)d_in[2];
    float* out         = (float*)d_out;

    // 296 CTAs x 512 threads: cid and cid+148 share an SM
    msda_kernel<<<296, 512>>>(value, loc, aw, out);
}